// round 3
// baseline (speedup 1.0000x reference)
#include <cuda_runtime.h>

#define S 8192
#define D 64
#define H 32        // b*n = 4*8
#define SCALE 0.125f // 64^-0.5
#define SCHUNK 512  // s elements per ctx block
#define TS 32       // s-tile inside ctx block

// Scratch (allocation-free rule: __device__ globals)
__device__ float g_C[H * D * D];  // per-head 64x64 context numerator
__device__ float g_Z[H * D];      // per-head row sums of exp(k)

// ---- packed f32x2 helpers ----
__device__ __forceinline__ unsigned long long pack2(float x, float y) {
    unsigned long long r;
    asm("mov.b64 %0, {%1, %2};" : "=l"(r) : "f"(x), "f"(y));
    return r;
}
__device__ __forceinline__ void unpack2(unsigned long long v, float &x, float &y) {
    asm("mov.b64 {%0, %1}, %2;" : "=f"(x), "=f"(y) : "l"(v));
}
__device__ __forceinline__ void fma2(unsigned long long &d, unsigned long long a,
                                     unsigned long long b) {
    asm("fma.rn.f32x2 %0, %1, %2, %0;" : "+l"(d) : "l"(a), "l"(b));
}
__device__ __forceinline__ unsigned long long mul2(unsigned long long a,
                                                   unsigned long long b) {
    unsigned long long r;
    asm("mul.rn.f32x2 %0, %1, %2;" : "=l"(r) : "l"(a), "l"(b));
    return r;
}

union F4U {
    float4 f;
    unsigned long long u[2];
    float s[4];
};

// ---- kernel 0: zero scratch ----
__global__ void zero_kernel() {
    int idx = blockIdx.x * blockDim.x + threadIdx.x;
    if (idx < H * D * D) g_C[idx] = 0.0f;
    if (idx < H * D) g_Z[idx] = 0.0f;
}

// ---- kernel 1: context numerator C[i][j] = sum_s exp(k[i,s]) * v[j,s], Z[i] = sum_s exp(k[i,s]) ----
__global__ __launch_bounds__(256) void ctx_kernel(const float* __restrict__ k,
                                                  const float* __restrict__ v) {
    __shared__ float ek[TS][D + 4];  // [s][i], exp(k)
    __shared__ float vs[TS][D + 4];  // [s][j]

    const int head = blockIdx.y;
    const int t = threadIdx.x;
    const float* kh = k + (size_t)head * D * S;
    const float* vh = v + (size_t)head * D * S;
    const int sblk = blockIdx.x * SCHUNK;

    const int ty = t >> 4, tx = t & 15;
    const int i0 = ty * 4, j0 = tx * 4;

    unsigned long long acc[4][2];
#pragma unroll
    for (int r = 0; r < 4; r++) { acc[r][0] = 0ull; acc[r][1] = 0ull; }

    float zloc = 0.0f;
    const int zi = t & 63;
    const int zs0 = (t >> 6) * 8;

    for (int tile = 0; tile < SCHUNK / TS; tile++) {
        const int sbase = sblk + tile * TS;
        // load + exp + transpose into smem (float4 over s, coalesced)
#pragma unroll
        for (int r = 0; r < 2; r++) {
            int idx = t + 256 * r;        // float4 index 0..511
            int i = idx >> 3;             // 0..63
            int s4 = (idx & 7) * 4;       // 0..28
            float4 kv = *reinterpret_cast<const float4*>(kh + (size_t)i * S + sbase + s4);
            ek[s4 + 0][i] = __expf(kv.x);
            ek[s4 + 1][i] = __expf(kv.y);
            ek[s4 + 2][i] = __expf(kv.z);
            ek[s4 + 3][i] = __expf(kv.w);
            float4 vv4 = *reinterpret_cast<const float4*>(vh + (size_t)i * S + sbase + s4);
            vs[s4 + 0][i] = vv4.x;
            vs[s4 + 1][i] = vv4.y;
            vs[s4 + 2][i] = vv4.z;
            vs[s4 + 3][i] = vv4.w;
        }
        __syncthreads();

        // partial Z accumulation (each thread: one row i, 8 s values)
#pragma unroll
        for (int s = 0; s < 8; s++) zloc += ek[zs0 + s][zi];

        // 64x64 outer-product accumulation over this s-tile (packed f32x2)
#pragma unroll
        for (int s = 0; s < TS; s++) {
            F4U ev, vv;
            ev.f = *reinterpret_cast<const float4*>(&ek[s][i0]);
            vv.f = *reinterpret_cast<const float4*>(&vs[s][j0]);
#pragma unroll
            for (int r = 0; r < 4; r++) {
                unsigned long long e2 = pack2(ev.s[r], ev.s[r]);
                fma2(acc[r][0], e2, vv.u[0]);
                fma2(acc[r][1], e2, vv.u[1]);
            }
        }
        __syncthreads();
    }

    // reduce partials into global scratch
    float* cptr = g_C + (size_t)head * D * D;
#pragma unroll
    for (int r = 0; r < 4; r++) {
        float x0, y0, x1, y1;
        unpack2(acc[r][0], x0, y0);
        unpack2(acc[r][1], x1, y1);
        atomicAdd(&cptr[(i0 + r) * D + j0 + 0], x0);
        atomicAdd(&cptr[(i0 + r) * D + j0 + 1], y0);
        atomicAdd(&cptr[(i0 + r) * D + j0 + 2], x1);
        atomicAdd(&cptr[(i0 + r) * D + j0 + 3], y1);
    }
    atomicAdd(&g_Z[head * D + zi], zloc);
}

// ---- kernel 2: out[j][s] = (scale/colsum[s]) * sum_i (C[i][j]/Z[i]) * exp(q[i][s]) ----
__global__ __launch_bounds__(256) void out_kernel(const float* __restrict__ q,
                                                  float* __restrict__ out) {
    __shared__ float Wt[D][D];       // Wt[i][j] = context[i][j]
    __shared__ float eq[D][D + 4];   // [i][s], exp(q)
    __shared__ float rz[D];
    __shared__ float rs[D];

    const int head = blockIdx.y;
    const int t = threadIdx.x;
    const int s0 = blockIdx.x * 64;
    const float* qh = q + (size_t)head * D * S;

    if (t < D) rz[t] = 1.0f / g_Z[head * D + t];
    __syncthreads();

    const float* Cg = g_C + (size_t)head * D * D;
#pragma unroll
    for (int r = 0; r < 16; r++) {
        int idx = t + 256 * r;   // 0..4095
        int i = idx >> 6;
        Wt[i][idx & 63] = Cg[idx] * rz[i];
    }

    // load q tile, exp, store [i][s]
#pragma unroll
    for (int r = 0; r < 4; r++) {
        int idx = t + 256 * r;        // float4 index 0..1023
        int i = idx >> 4;             // 0..63
        int s4 = (idx & 15) * 4;      // 0..60
        float4 qv = *reinterpret_cast<const float4*>(qh + (size_t)i * S + s0 + s4);
        float4 e;
        e.x = __expf(qv.x);
        e.y = __expf(qv.y);
        e.z = __expf(qv.z);
        e.w = __expf(qv.w);
        *reinterpret_cast<float4*>(&eq[i][s4]) = e;
    }
    __syncthreads();

    // column softmax denominators over d
    if (t < D) {
        float sum = 0.0f;
#pragma unroll
        for (int i = 0; i < D; i++) sum += eq[i][t];
        rs[t] = SCALE / sum;
    }
    __syncthreads();

    const int ty = t >> 4, tx = t & 15;
    const int j0 = ty * 4, sl0 = tx * 4;

    unsigned long long acc[4][2];
#pragma unroll
    for (int r = 0; r < 4; r++) { acc[r][0] = 0ull; acc[r][1] = 0ull; }

#pragma unroll
    for (int i = 0; i < D; i++) {
        F4U w, qv;
        w.f = *reinterpret_cast<const float4*>(&Wt[i][j0]);
        qv.f = *reinterpret_cast<const float4*>(&eq[i][sl0]);
#pragma unroll
        for (int r = 0; r < 4; r++) {
            unsigned long long w2 = pack2(w.s[r], w.s[r]);
            fma2(acc[r][0], w2, qv.u[0]);
            fma2(acc[r][1], w2, qv.u[1]);
        }
    }

    F4U rsv;
    rsv.f = *reinterpret_cast<const float4*>(&rs[sl0]);
    float* oh = out + (size_t)head * D * S;
#pragma unroll
    for (int r = 0; r < 4; r++) {
        F4U o;
        o.u[0] = mul2(acc[r][0], rsv.u[0]);
        o.u[1] = mul2(acc[r][1], rsv.u[1]);
        *reinterpret_cast<float4*>(oh + (size_t)(j0 + r) * S + s0 + sl0) = o.f;
    }
}

extern "C" void kernel_launch(void* const* d_in, const int* in_sizes, int n_in,
                              void* d_out, int out_size) {
    const float* q = (const float*)d_in[0];
    const float* k = (const float*)d_in[1];
    const float* v = (const float*)d_in[2];
    float* out = (float*)d_out;

    zero_kernel<<<(H * D * D + 255) / 256, 256>>>();
    dim3 g1(S / SCHUNK, H);   // 16 x 32 = 512 blocks
    ctx_kernel<<<g1, 256>>>(k, v);
    dim3 g2(S / 64, H);       // 128 x 32 = 4096 blocks
    out_kernel<<<g2, 256>>>(q, out);
}

// round 6
// speedup vs baseline: 1.1300x; 1.1300x over previous
#include <cuda_runtime.h>
#include <cuda_bf16.h>
#include <cstdint>

#define S 8192
#define D 64
#define H 32
#define SCALEF 0.125f
#define NCHUNK 8
#define SCH 1024
#define KT 64
#define PA 72          // bf16 elements per row (144B, 16B-aligned, conflict-free ldmatrix)
#define PAB (PA * 2)   // row pitch in bytes = 144

// ---- scratch (allocation-free rule) ----
__device__ float g_Cp[NCHUNK][H * D * D];
__device__ float g_Zp[NCHUNK][H * D];
__device__ float g_C[H * D * D];
__device__ float g_Z[H * D];

// ---------------- helpers ----------------
__device__ __forceinline__ uint32_t smem_u32(const void* p) {
    uint32_t a;
    asm("{ .reg .u64 t; cvta.to.shared.u64 t, %1; cvt.u32.u64 %0, t; }" : "=r"(a) : "l"(p));
    return a;
}
__device__ __forceinline__ void ldm_x4(uint32_t a, uint32_t& r0, uint32_t& r1, uint32_t& r2, uint32_t& r3) {
    asm volatile("ldmatrix.sync.aligned.m8n8.x4.shared.b16 {%0,%1,%2,%3}, [%4];"
                 : "=r"(r0), "=r"(r1), "=r"(r2), "=r"(r3) : "r"(a));
}
__device__ __forceinline__ void ldm_x4_t(uint32_t a, uint32_t& r0, uint32_t& r1, uint32_t& r2, uint32_t& r3) {
    asm volatile("ldmatrix.sync.aligned.m8n8.x4.trans.shared.b16 {%0,%1,%2,%3}, [%4];"
                 : "=r"(r0), "=r"(r1), "=r"(r2), "=r"(r3) : "r"(a));
}
__device__ __forceinline__ void mma16816(float* c, uint32_t a0, uint32_t a1, uint32_t a2, uint32_t a3,
                                         uint32_t b0, uint32_t b1) {
    asm volatile("mma.sync.aligned.m16n8k16.row.col.f32.bf16.bf16.f32 "
                 "{%0,%1,%2,%3},{%4,%5,%6,%7},{%8,%9},{%0,%1,%2,%3};"
                 : "+f"(c[0]), "+f"(c[1]), "+f"(c[2]), "+f"(c[3])
                 : "r"(a0), "r"(a1), "r"(a2), "r"(a3), "r"(b0), "r"(b1));
}
// pack (lo=x0, hi=x1) as bf16x2
__device__ __forceinline__ uint32_t packbf(float x0, float x1) {
    uint32_t r;
    asm("cvt.rn.bf16x2.f32 %0, %1, %2;" : "=r"(r) : "f"(x1), "f"(x0));
    return r;
}
__device__ __forceinline__ void split2(float x0, float x1, uint32_t& hi, uint32_t& lo) {
    hi = packbf(x0, x1);
    float h0 = __uint_as_float(hi << 16);
    float h1 = __uint_as_float(hi & 0xFFFF0000u);
    lo = packbf(x0 - h0, x1 - h1);
}

// =======================================================================
// kernel 1: C_partial[i][j] = sum_s exp(k[i,s]) * v[j,s]   (per head, per s-chunk)
// 3 HMMA chains (hi*hi + lo*hi + hi*lo) into one fp32 accumulator.
// =======================================================================
__global__ __launch_bounds__(256) void ctx_kernel(const float* __restrict__ k,
                                                  const float* __restrict__ v) {
    __shared__ __align__(16) __nv_bfloat16 sm[4 * 64 * PA];
    __shared__ float zrow[64];
    // byte offsets of the 4 tiles
    const uint32_t EHI = 0, ELO = 64 * PAB, VHI = 2 * 64 * PAB, VLO = 3 * 64 * PAB;

    const int head = blockIdx.y, chunk = blockIdx.x;
    const int t = threadIdx.x, w = t >> 5, l = t & 31;
    const int mw = w >> 1, nw = w & 1;
    const float* kh = k + (size_t)head * D * S + chunk * SCH;
    const float* vh = v + (size_t)head * D * S + chunk * SCH;

    if (t < 64) zrow[t] = 0.0f;
    const uint32_t sb = smem_u32(sm);

    // lane constants for ldmatrix addressing
    const int lm = l & 15, lq = l >> 4;
    const uint32_t aoff = (uint32_t)(16 * mw + lm) * PAB + 16 * lq;      // A: row-major [m][k]
    const int nrow = (l & 7) + 8 * lq;                                    // B: [n][k] row-major
    const int kq = (l >> 3) & 1;

    float acc[4][4];
#pragma unroll
    for (int a = 0; a < 4; a++)
#pragma unroll
        for (int b = 0; b < 4; b++) acc[a][b] = 0.0f;

    __syncthreads();

    for (int tile = 0; tile < SCH / KT; ++tile) {
        const float* kt = kh + tile * KT;
        const float* vt = vh + tile * KT;
#pragma unroll
        for (int r = 0; r < 4; r++) {
            int idx = t + 256 * r;
            int i = idx >> 4;
            int s4 = (idx & 15) * 4;
            float4 a = *(const float4*)(kt + (size_t)i * S + s4);
            float e0 = __expf(a.x), e1 = __expf(a.y), e2 = __expf(a.z), e3 = __expf(a.w);
            float p = (e0 + e1) + (e2 + e3);
            p += __shfl_xor_sync(0xffffffffu, p, 1);
            p += __shfl_xor_sync(0xffffffffu, p, 2);
            p += __shfl_xor_sync(0xffffffffu, p, 4);
            p += __shfl_xor_sync(0xffffffffu, p, 8);
            if ((l & 15) == 0) atomicAdd(&zrow[i], p);
            uint32_t h0, l0, h1, l1;
            split2(e0, e1, h0, l0);
            split2(e2, e3, h1, l1);
            *(uint2*)((char*)sm + EHI + i * PAB + s4 * 2) = make_uint2(h0, h1);
            *(uint2*)((char*)sm + ELO + i * PAB + s4 * 2) = make_uint2(l0, l1);
            float4 b = *(const float4*)(vt + (size_t)i * S + s4);
            split2(b.x, b.y, h0, l0);
            split2(b.z, b.w, h1, l1);
            *(uint2*)((char*)sm + VHI + i * PAB + s4 * 2) = make_uint2(h0, h1);
            *(uint2*)((char*)sm + VLO + i * PAB + s4 * 2) = make_uint2(l0, l1);
        }
        __syncthreads();

#pragma unroll
        for (int ks = 0; ks < 4; ks++) {
            uint32_t ah[4], al[4], bh[8], bl[8];
            uint32_t aA = sb + aoff + 32 * ks;
            ldm_x4(aA + EHI, ah[0], ah[1], ah[2], ah[3]);
            ldm_x4(aA + ELO, al[0], al[1], al[2], al[3]);
            uint32_t b0 = sb + (uint32_t)(32 * nw + nrow) * PAB + 16 * kq + 32 * ks;
            uint32_t b1 = sb + (uint32_t)(32 * nw + 16 + nrow) * PAB + 16 * kq + 32 * ks;
            ldm_x4(b0 + VHI, bh[0], bh[1], bh[2], bh[3]);
            ldm_x4(b1 + VHI, bh[4], bh[5], bh[6], bh[7]);
            ldm_x4(b0 + VLO, bl[0], bl[1], bl[2], bl[3]);
            ldm_x4(b1 + VLO, bl[4], bl[5], bl[6], bl[7]);
#pragma unroll
            for (int ns = 0; ns < 4; ns++) {
                mma16816(acc[ns], ah[0], ah[1], ah[2], ah[3], bh[2 * ns], bh[2 * ns + 1]);
                mma16816(acc[ns], al[0], al[1], al[2], al[3], bh[2 * ns], bh[2 * ns + 1]);
                mma16816(acc[ns], ah[0], ah[1], ah[2], ah[3], bl[2 * ns], bl[2 * ns + 1]);
            }
        }
        __syncthreads();
    }

    // store partial C (full overwrite, no init needed)
    float* cp = g_Cp[chunk] + (size_t)head * D * D;
    const int r0 = 16 * mw + (l >> 2);
#pragma unroll
    for (int ns = 0; ns < 4; ns++) {
        int col = 32 * nw + 8 * ns + 2 * (l & 3);
        *(float2*)(cp + r0 * 64 + col) = make_float2(acc[ns][0], acc[ns][1]);
        *(float2*)(cp + (r0 + 8) * 64 + col) = make_float2(acc[ns][2], acc[ns][3]);
    }
    if (t < 64) g_Zp[chunk][head * 64 + t] = zrow[t];
}

// =======================================================================
// kernel R: reduce partials
// =======================================================================
__global__ __launch_bounds__(256) void reduce_kernel() {
    int gi = blockIdx.x * 256 + threadIdx.x;
    float s = 0.f;
#pragma unroll
    for (int p = 0; p < NCHUNK; p++) s += g_Cp[p][gi];
    g_C[gi] = s;
    if (gi < H * D) {
        float z = 0.f;
#pragma unroll
        for (int p = 0; p < NCHUNK; p++) z += g_Zp[p][gi];
        g_Z[gi] = z;
    }
}

// =======================================================================
// kernel 2: out[j][s] = rs[s] * sum_i W[i][j] * exp(q[i][s]),  W = C/Z
// A = Wt (rows j, k=i), B = eq [i][s] via ldmatrix.trans. 3 chains, 1 accum.
// s-tile 128, processed in two 64-col halves (static smem < 48KB).
// =======================================================================
__global__ __launch_bounds__(256) void out_kernel(const float* __restrict__ q,
                                                  float* __restrict__ out) {
    __shared__ __align__(16) __nv_bfloat16 smA[128 * PA];      // rows 0-63: Whi(j,i); 64-127: Wlo
    __shared__ __align__(16) __nv_bfloat16 smB[2 * 64 * PA];   // eqhi [i][s64]; eqlo
    __shared__ float rz[64];
    __shared__ float rsv[128];

    const int head = blockIdx.y;
    const int s0 = blockIdx.x * 128;
    const int t = threadIdx.x, w = t >> 5, l = t & 31;
    const int mw = w >> 1, nw = w & 1;
    const float* qh = q + (size_t)head * D * S;

    if (t < 64) rz[t] = 1.0f / g_Z[head * 64 + t];
    __syncthreads();

    // stage A: W = C * rz, hi/lo split, transposed [j][i]
    const float* Cg = g_C + (size_t)head * D * D;
#pragma unroll
    for (int r = 0; r < 16; r++) {
        int idx = t + 256 * r;
        int i = idx >> 6, j = idx & 63;
        float wv = Cg[idx] * rz[i];
        __nv_bfloat16 hb = __float2bfloat16(wv);
        float hf = __bfloat162float(hb);
        smA[j * PA + i] = hb;
        smA[(64 + j) * PA + i] = __float2bfloat16(wv - hf);
    }

    float acc[2][4][4];
#pragma unroll
    for (int h = 0; h < 2; h++)
#pragma unroll
        for (int a = 0; a < 4; a++)
#pragma unroll
            for (int b = 0; b < 4; b++) acc[h][a][b] = 0.0f;

    const uint32_t sa = smem_u32(smA), sbB = smem_u32(smB);
    const uint32_t BLO = 64 * PAB;
    const int lm = l & 15, lq = l >> 4;

    for (int half = 0; half < 2; half++) {
        __syncthreads();  // A staged (half 0) / previous-half MMA done (half 1)
        // stage eq for this 64-col half
#pragma unroll
        for (int r = 0; r < 4; r++) {
            int idx = t + 256 * r;
            int i = idx >> 4;
            int s4 = (idx & 15) * 4;
            float4 a = *(const float4*)(qh + (size_t)i * S + s0 + 64 * half + s4);
            float e0 = __expf(a.x), e1 = __expf(a.y), e2 = __expf(a.z), e3 = __expf(a.w);
            uint32_t h0, l0, h1, l1;
            split2(e0, e1, h0, l0);
            split2(e2, e3, h1, l1);
            *(uint2*)((char*)smB + i * PAB + s4 * 2) = make_uint2(h0, h1);
            *(uint2*)((char*)smB + BLO + i * PAB + s4 * 2) = make_uint2(l0, l1);
        }
        __syncthreads();
        // column softmax denominators for this half
        if (t < 64) {
            float sum = 0.f;
#pragma unroll
            for (int i = 0; i < 64; i++)
                sum += __bfloat162float(smB[i * PA + t]) + __bfloat162float(smB[64 * PA + i * PA + t]);
            rsv[64 * half + t] = SCALEF / sum;
        }
        // MMA: K = i = 64 -> 4 k-steps
#pragma unroll
        for (int ks = 0; ks < 4; ks++) {
            uint32_t ah[4], al[4], bh[8], bl[8];
            uint32_t aA = sa + (uint32_t)(16 * mw + lm) * PAB + 16 * lq + 32 * ks;
            ldm_x4(aA, ah[0], ah[1], ah[2], ah[3]);
            ldm_x4(aA + 64 * PAB, al[0], al[1], al[2], al[3]);
            uint32_t bbase = sbB + (uint32_t)(16 * ks + lm) * PAB;
            uint32_t b0 = bbase + (uint32_t)(32 * nw + 8 * lq) * 2;
            uint32_t b1 = bbase + (uint32_t)(32 * nw + 16 + 8 * lq) * 2;
            ldm_x4_t(b0, bh[0], bh[1], bh[2], bh[3]);
            ldm_x4_t(b1, bh[4], bh[5], bh[6], bh[7]);
            ldm_x4_t(b0 + BLO, bl[0], bl[1], bl[2], bl[3]);
            ldm_x4_t(b1 + BLO, bl[4], bl[5], bl[6], bl[7]);
#pragma unroll
            for (int ns = 0; ns < 4; ns++) {
                mma16816(acc[half][ns], ah[0], ah[1], ah[2], ah[3], bh[2 * ns], bh[2 * ns + 1]);
                mma16816(acc[half][ns], al[0], al[1], al[2], al[3], bh[2 * ns], bh[2 * ns + 1]);
                mma16816(acc[half][ns], ah[0], ah[1], ah[2], ah[3], bl[2 * ns], bl[2 * ns + 1]);
            }
        }
    }
    __syncthreads();  // rsv visible to all

    float* oh = out + (size_t)head * D * S;
    const int j0 = 16 * mw + (l >> 2);
#pragma unroll
    for (int half = 0; half < 2; half++) {
#pragma unroll
        for (int ns = 0; ns < 4; ns++) {
            int col = 64 * half + 32 * nw + 8 * ns + 2 * (l & 3);
            float r0 = rsv[col], r1 = rsv[col + 1];
            *(float2*)(oh + (size_t)j0 * S + s0 + col) =
                make_float2(acc[half][ns][0] * r0, acc[half][ns][1] * r1);
            *(float2*)(oh + (size_t)(j0 + 8) * S + s0 + col) =
                make_float2(acc[half][ns][2] * r0, acc[half][ns][3] * r1);
        }
    }
}

extern "C" void kernel_launch(void* const* d_in, const int* in_sizes, int n_in,
                              void* d_out, int out_size) {
    const float* q = (const float*)d_in[0];
    const float* k = (const float*)d_in[1];
    const float* v = (const float*)d_in[2];
    float* out = (float*)d_out;

    dim3 g1(NCHUNK, H);          // 8 x 32 = 256 CTAs
    ctx_kernel<<<g1, 256>>>(k, v);
    reduce_kernel<<<(H * D * D) / 256, 256>>>();
    dim3 g2(S / 128, H);         // 64 x 32 = 2048 CTAs
    out_kernel<<<g2, 256>>>(q, out);
}